// round 2
// baseline (speedup 1.0000x reference)
#include <cuda_runtime.h>
#include <cuda_bf16.h>

// Problem constants (shapes from reference): N=50000, D_IN=256, D_OUT=128, DEG=16
#define D_IN  256
#define D_OUT 128
#define MAX_N 50000

// Scratch for Xp = X @ W  (25.6 MB) — __device__ global, no allocation.
__device__ float g_Xp[MAX_N * D_OUT];

// ---------------------------------------------------------------------------
// Kernel 1: SGEMM  C[M x 128] = A[M x 256] * B[256 x 128]  (fp32)
// Tiling: BM=128, BN=128, BK=16; 256 threads; 8x8 register micro-tile.
// ---------------------------------------------------------------------------
#define BM 128
#define BN 128
#define BK 16
#define TM 8
#define TN 8

__global__ __launch_bounds__(256, 2)
void gemm_kernel(const float* __restrict__ A, const float* __restrict__ B, int M) {
    __shared__ float As[BK][BM];   // transposed A tile
    __shared__ float Bs[BK][BN];

    const int tid = threadIdx.x;           // 0..255
    const int m0  = blockIdx.x * BM;
    const int ty  = tid >> 4;              // 0..15
    const int tx  = tid & 15;              // 0..15

    float acc[TM][TN];
#pragma unroll
    for (int i = 0; i < TM; i++)
#pragma unroll
        for (int j = 0; j < TN; j++) acc[i][j] = 0.f;

    for (int k0 = 0; k0 < D_IN; k0 += BK) {
        // ---- load A tile (128 rows x 16 cols) as 512 float4, 2 per thread,
        //      store transposed into As[k][m]
#pragma unroll
        for (int t = 0; t < 2; t++) {
            int i  = tid + t * 256;        // 0..511
            int r  = i >> 2;               // row in tile 0..127
            int cv = i & 3;                // which float4 along K
            int grow = m0 + r;
            float4 v = make_float4(0.f, 0.f, 0.f, 0.f);
            if (grow < M)
                v = *reinterpret_cast<const float4*>(&A[(size_t)grow * D_IN + k0 + cv * 4]);
            As[cv * 4 + 0][r] = v.x;
            As[cv * 4 + 1][r] = v.y;
            As[cv * 4 + 2][r] = v.z;
            As[cv * 4 + 3][r] = v.w;
        }
        // ---- load B tile (16 rows x 128 cols) as 512 float4, 2 per thread
#pragma unroll
        for (int t = 0; t < 2; t++) {
            int i  = tid + t * 256;        // 0..511
            int r  = i >> 5;               // 0..15
            int cv = i & 31;               // 0..31
            float4 v = *reinterpret_cast<const float4*>(&B[(size_t)(k0 + r) * D_OUT + cv * 4]);
            reinterpret_cast<float4*>(&Bs[r][0])[cv] = v;
        }
        __syncthreads();

#pragma unroll
        for (int k = 0; k < BK; k++) {
            float a[TM], b[TN];
            float4 a0 = reinterpret_cast<const float4*>(&As[k][ty * TM])[0];
            float4 a1 = reinterpret_cast<const float4*>(&As[k][ty * TM])[1];
            a[0]=a0.x; a[1]=a0.y; a[2]=a0.z; a[3]=a0.w;
            a[4]=a1.x; a[5]=a1.y; a[6]=a1.z; a[7]=a1.w;
            float4 b0 = reinterpret_cast<const float4*>(&Bs[k][tx * TN])[0];
            float4 b1 = reinterpret_cast<const float4*>(&Bs[k][tx * TN])[1];
            b[0]=b0.x; b[1]=b0.y; b[2]=b0.z; b[3]=b0.w;
            b[4]=b1.x; b[5]=b1.y; b[6]=b1.z; b[7]=b1.w;
#pragma unroll
            for (int i = 0; i < TM; i++)
#pragma unroll
                for (int j = 0; j < TN; j++)
                    acc[i][j] = fmaf(a[i], b[j], acc[i][j]);
        }
        __syncthreads();
    }

    // ---- store 8x8 tile (two float4 per row)
#pragma unroll
    for (int i = 0; i < TM; i++) {
        int grow = m0 + ty * TM + i;
        if (grow < M) {
            float4 v0 = make_float4(acc[i][0], acc[i][1], acc[i][2], acc[i][3]);
            float4 v1 = make_float4(acc[i][4], acc[i][5], acc[i][6], acc[i][7]);
            float4* dst = reinterpret_cast<float4*>(&g_Xp[(size_t)grow * D_OUT + tx * TN]);
            dst[0] = v0;
            dst[1] = v1;
        }
    }
}

// ---------------------------------------------------------------------------
// Kernel 2: SpMM  out[i] = sum_{e in row i} Xp[col[e]]
// One warp per row; each lane owns one float4 (4 of the 128 output cols).
// Unroll-by-4 over edges for MLP (independent gathers hide L2 latency).
// ---------------------------------------------------------------------------
__global__ __launch_bounds__(256)
void spmm_kernel(const int* __restrict__ rowptr, const int* __restrict__ colidx,
                 float* __restrict__ out, int M) {
    const int warp = (blockIdx.x * blockDim.x + threadIdx.x) >> 5;
    const int lane = threadIdx.x & 31;
    if (warp >= M) return;

    const int start = __ldg(&rowptr[warp]);
    const int end   = __ldg(&rowptr[warp + 1]);

    const float4* __restrict__ Xp4 = reinterpret_cast<const float4*>(g_Xp);

    float4 acc = make_float4(0.f, 0.f, 0.f, 0.f);
    int e = start;
    for (; e + 4 <= end; e += 4) {
        int c0 = __ldg(&colidx[e + 0]);
        int c1 = __ldg(&colidx[e + 1]);
        int c2 = __ldg(&colidx[e + 2]);
        int c3 = __ldg(&colidx[e + 3]);
        float4 v0 = Xp4[(size_t)c0 * 32 + lane];
        float4 v1 = Xp4[(size_t)c1 * 32 + lane];
        float4 v2 = Xp4[(size_t)c2 * 32 + lane];
        float4 v3 = Xp4[(size_t)c3 * 32 + lane];
        acc.x += v0.x + v1.x + v2.x + v3.x;
        acc.y += v0.y + v1.y + v2.y + v3.y;
        acc.z += v0.z + v1.z + v2.z + v3.z;
        acc.w += v0.w + v1.w + v2.w + v3.w;
    }
    for (; e < end; e++) {
        int c = __ldg(&colidx[e]);
        float4 v = Xp4[(size_t)c * 32 + lane];
        acc.x += v.x; acc.y += v.y; acc.z += v.z; acc.w += v.w;
    }

    reinterpret_cast<float4*>(out)[(size_t)warp * 32 + lane] = acc;
}

// ---------------------------------------------------------------------------
// Launch
// Inputs (metadata order): X, weights, row_pointers, column_index, ...
// ---------------------------------------------------------------------------
extern "C" void kernel_launch(void* const* d_in, const int* in_sizes, int n_in,
                              void* d_out, int out_size) {
    const float* X  = (const float*)d_in[0];
    const float* W  = (const float*)d_in[1];
    const int*   rp = (const int*)d_in[2];
    const int*   ci = (const int*)d_in[3];
    float* out = (float*)d_out;

    const int M = in_sizes[0] / D_IN;   // 50000

    dim3 gemm_grid((M + BM - 1) / BM);
    gemm_kernel<<<gemm_grid, 256>>>(X, W, M);

    int warps_per_block = 256 / 32;
    dim3 spmm_grid((M + warps_per_block - 1) / warps_per_block);
    spmm_kernel<<<spmm_grid, 256>>>(rp, ci, out, M);
}